// round 11
// baseline (speedup 1.0000x reference)
#include <cuda_runtime.h>
#include <cuda_bf16.h>
#include <math.h>
#include <stdint.h>

#define E_DIM 256
#define N_MAX 8192
#define TILE 128
#define CHUNK 64
#define NCHUNK (E_DIM / CHUNK)      // 4
#define NSTAGE 3
#define SAW 72                       // smem row stride in bf16 (144B)
#define STAGE_BYTES (TILE * SAW * 2) // 18432

// ---------------- device scratch ----------------
__device__ __nv_bfloat16 g_xb[N_MAX * E_DIM];
__device__ __nv_bfloat16 g_P[N_MAX * E_DIM];
__device__ __nv_bfloat16 g_Q[N_MAX * E_DIM];
__device__ int      g_target[N_MAX];
__device__ int      g_rowsL[N_MAX];
__device__ int      g_rowsN[N_MAX];
__device__ float    g_S[4][E_DIM];
__device__ int      g_cntL, g_cntN, g_padL, g_padN;
__device__ double   g_base;
__device__ double   g_sum;
__device__ unsigned g_done;

// ---------------- helpers ----------------
__device__ __forceinline__ uint32_t smem_u32(const void* p) {
    uint32_t a;
    asm("{ .reg .u64 t; cvta.to.shared.u64 t, %1; cvt.u32.u64 %0, t; }" : "=r"(a) : "l"(p));
    return a;
}
__device__ __forceinline__ void cp_async16(uint32_t dst, const void* src) {
    asm volatile("cp.async.cg.shared.global [%0], [%1], 16;" :: "r"(dst), "l"(src) : "memory");
}
__device__ __forceinline__ void cp_commit() {
    asm volatile("cp.async.commit_group;" ::: "memory");
}
__device__ __forceinline__ void cp_wait1() {
    asm volatile("cp.async.wait_group 1;" ::: "memory");
}
__device__ __forceinline__ void ldsm_x4(uint32_t* r, uint32_t addr) {
    asm volatile("ldmatrix.sync.aligned.m8n8.x4.shared.b16 {%0,%1,%2,%3}, [%4];"
                 : "=r"(r[0]), "=r"(r[1]), "=r"(r[2]), "=r"(r[3]) : "r"(addr));
}
__device__ __forceinline__ void mma_16816(float* d, const uint32_t* a, const uint32_t* b) {
    asm volatile(
        "mma.sync.aligned.m16n8k16.row.col.f32.bf16.bf16.f32 "
        "{%0,%1,%2,%3}, {%4,%5,%6,%7}, {%8,%9}, {%0,%1,%2,%3};"
        : "+f"(d[0]), "+f"(d[1]), "+f"(d[2]), "+f"(d[3])
        : "r"(a[0]), "r"(a[1]), "r"(a[2]), "r"(a[3]), "r"(b[0]), "r"(b[1]));
}

// ---------------- K1: normalize (warp per row) + block 0 target decode ----------------
__global__ void prep_kernel(const float* __restrict__ x, const int* __restrict__ traw, int n) {
    const int tid = threadIdx.x;
    const int row = blockIdx.x * 8 + (tid >> 5);
    const int lane = tid & 31;

    const float4* src = (const float4*)(x + (size_t)row * E_DIM + lane * 8);
    float4 v0 = src[0];
    float4 v1 = src[1];
    float s = v0.x * v0.x + v0.y * v0.y + v0.z * v0.z + v0.w * v0.w
            + v1.x * v1.x + v1.y * v1.y + v1.z * v1.z + v1.w * v1.w;
    #pragma unroll
    for (int o = 16; o > 0; o >>= 1) s += __shfl_xor_sync(0xffffffffu, s, o);
    const float inv = 1.0f / fmaxf(sqrtf(s), 1e-8f);

    uint32_t p[4];
    p[0] = (uint32_t)__bfloat16_as_ushort(__float2bfloat16(v0.x * inv))
         | ((uint32_t)__bfloat16_as_ushort(__float2bfloat16(v0.y * inv)) << 16);
    p[1] = (uint32_t)__bfloat16_as_ushort(__float2bfloat16(v0.z * inv))
         | ((uint32_t)__bfloat16_as_ushort(__float2bfloat16(v0.w * inv)) << 16);
    p[2] = (uint32_t)__bfloat16_as_ushort(__float2bfloat16(v1.x * inv))
         | ((uint32_t)__bfloat16_as_ushort(__float2bfloat16(v1.y * inv)) << 16);
    p[3] = (uint32_t)__bfloat16_as_ushort(__float2bfloat16(v1.z * inv))
         | ((uint32_t)__bfloat16_as_ushort(__float2bfloat16(v1.w * inv)) << 16);
    *(uint4*)(g_xb + (size_t)row * E_DIM + lane * 8) = make_uint4(p[0], p[1], p[2], p[3]);

    if (blockIdx.x == 0) {
        __shared__ int s_flag;
        if (tid == 0) { s_flag = 0; g_sum = 0.0; g_done = 0u; }
        for (int i = tid; i < 4 * E_DIM; i += blockDim.x) ((float*)g_S)[i] = 0.f;
        __syncthreads();
        int f = 0;
        for (int i = 2 * tid + 1; i < n; i += 2 * blockDim.x)
            if (traw[i] != 0) f = 1;
        if (f) atomicOr(&s_flag, 1);
        __syncthreads();
        const int is64 = (s_flag == 0);
        for (int i = tid; i < n; i += blockDim.x)
            g_target[i] = is64 ? traw[2 * i] : traw[i];
    }
}

// ---------------- K2: per-class sums (64 rows per block) ----------------
__global__ void classsum_kernel(int n) {
    const int t = threadIdx.x;          // dim
    const int r0 = blockIdx.x * 64;
    float a0 = 0.f, a1 = 0.f, a2 = 0.f, a3 = 0.f;
    #pragma unroll 4
    for (int r = 0; r < 64; r++) {
        const int row = r0 + r;
        const float v = __bfloat162float(g_xb[row * E_DIM + t]);
        const int c = g_target[row];
        if (c == 0) a0 += v; else if (c == 1) a1 += v; else if (c == 2) a2 += v; else a3 += v;
    }
    atomicAdd(&g_S[0][t], a0);
    atomicAdd(&g_S[1][t], a1);
    atomicAdd(&g_S[2][t], a2);
    atomicAdd(&g_S[3][t], a3);
}

// ---------------- K3: closed-form same-class loss + gather lists ----------------
__global__ void scalar_kernel(int n, float* __restrict__ out, double invN) {
    const int t = threadIdx.x;
    __shared__ int cnt[4];
    __shared__ int sL, sN, Lsh;
    __shared__ float sacc[8];
    if (t < 4) cnt[t] = 0;
    if (t < 8) sacc[t] = 0.f;
    if (t == 0) { sL = 0; sN = 0; }
    __syncthreads();

    for (int i = t; i < n; i += blockDim.x) atomicAdd(&cnt[g_target[i] & 3], 1);
    __syncthreads();
    if (t == 0) Lsh = (cnt[3] > 0) ? 3 : (cnt[2] > 0) ? 2 : (cnt[1] > 0) ? 1 : 0;
    __syncthreads();
    const int L = Lsh;

    for (int i = t; i < n; i += blockDim.x) {
        if (g_target[i] == L) g_rowsL[atomicAdd(&sL, 1)] = i;
        else                  g_rowsN[atomicAdd(&sN, 1)] = i;
    }

    const float s0 = g_S[0][t], s1 = g_S[1][t], s2 = g_S[2][t], s3 = g_S[3][t];
    const float sAll = s0 + s1 + s2 + s3;
    const float si[4] = {s0, s1, s2, s3};
    #pragma unroll
    for (int i = 0; i < 4; i++) {
        atomicAdd(&sacc[i], si[i] * si[i]);
        const float cd = sAll - si[i];
        atomicAdd(&sacc[4 + i], cd * cd);
    }
    __syncthreads();

    if (t == 0) {
        double base = 0.0;
        for (int i = 0; i < 4; i++) {
            const double m = (double)cnt[i];
            if (cnt[i] > 0) {
                const double M = (double)n - m;
                const double pairs = m * (m - 1.0) * 0.5 + M * (M - 1.0) * 0.5;
                const double sumcos = ((double)sacc[i] - m) * 0.5 + ((double)sacc[4 + i] - M) * 0.5;
                base += (pairs - sumcos) / m;
            }
        }
        g_base = base;
        g_cntL = sL;
        g_cntN = sN;
        g_padL = (sL + 127) & ~127;
        g_padN = (sN + 127) & ~127;
        // degenerate case: no cross-class pairs -> margin sum is 0, write out here
        if (sN == 0) out[0] = (float)(base * invN);
    }
}

// ---------------- K4: gather rows into P / Q (stride loop) ----------------
__global__ void gather_kernel() {
    const int padL = g_padL, padN = g_padN, cntL = g_cntL, cntN = g_cntN;
    const int totalVec = (padL + padN) * 32;   // 32 uint4 per row
    for (int v = blockIdx.x * blockDim.x + threadIdx.x; v < totalVec;
         v += gridDim.x * blockDim.x) {
        const int row = v >> 5;
        const int q = v & 31;
        uint4 val = make_uint4(0u, 0u, 0u, 0u);
        uint4* dst;
        if (row < padL) {
            if (row < cntL) val = ((const uint4*)(g_xb + (size_t)g_rowsL[row] * E_DIM))[q];
            dst = (uint4*)(g_P + (size_t)row * E_DIM);
        } else {
            const int r2 = row - padL;
            if (r2 < cntN) val = ((const uint4*)(g_xb + (size_t)g_rowsN[r2] * E_DIM))[q];
            dst = (uint4*)(g_Q + (size_t)r2 * E_DIM);
        }
        dst[q] = val;
    }
}

// ---------------- K5: relu-margin GEMM over P x Q^T, fused finalize ----------------
#define OFF_RED  0
#define OFF_A    1536
#define OFF_B    (OFF_A + NSTAGE * STAGE_BYTES)
#define SMEM_TOTAL (OFF_B + NSTAGE * STAGE_BYTES)

__global__ __launch_bounds__(256, 2) void relu_kernel(float* __restrict__ out, double invN) {
    const int bi = blockIdx.y;
    const int bj = blockIdx.x;
    const int padL = g_padL, padN = g_padN;
    if (bi * TILE >= padL || bj * TILE >= padN) return;

    extern __shared__ char smem[];
    const uint32_t sbase = smem_u32(smem);
    const int tid = threadIdx.x;
    const int wid = tid >> 5;
    const int lid = tid & 31;

    const uint4* __restrict__ srcA = (const uint4*)(g_P + (size_t)bi * TILE * E_DIM);
    const uint4* __restrict__ srcB = (const uint4*)(g_Q + (size_t)bj * TILE * E_DIM);

    auto load_chunk = [&](int c) {
        if (c < NCHUNK) {
            const int stage = c % NSTAGE;
            const uint32_t dA = sbase + OFF_A + stage * STAGE_BYTES;
            const uint32_t dB = sbase + OFF_B + stage * STAGE_BYTES;
            #pragma unroll
            for (int it = 0; it < 4; it++) {
                int v = tid + it * 256;
                int row = v >> 3;
                int q = v & 7;
                uint32_t d = (uint32_t)(row * SAW + q * 8) * 2u;
                int gsrc = row * 32 + c * 8 + q;
                cp_async16(dA + d, srcA + gsrc);
                cp_async16(dB + d, srcB + gsrc);
            }
        }
        cp_commit();
    };

    load_chunk(0);
    load_chunk(1);

    const int wm = wid & 1;
    const int wn = wid >> 1;
    const int rbase = wm * 64;
    const int cbase = wn * 32;

    float acc[4][4][4];
    #pragma unroll
    for (int mt = 0; mt < 4; mt++)
        #pragma unroll
        for (int nt = 0; nt < 4; nt++)
            #pragma unroll
            for (int q = 0; q < 4; q++) acc[mt][nt][q] = 0.f;

    const int mi = lid >> 3;
    const int mr = lid & 7;
    const uint32_t aOff = (uint32_t)((rbase + mr + (mi & 1) * 8) * SAW + (mi >> 1) * 8) * 2u;
    const uint32_t bOff = (uint32_t)((cbase + mr + (mi >> 1) * 8) * SAW + (mi & 1) * 8) * 2u;

    #pragma unroll
    for (int c = 0; c < NCHUNK; c++) {
        const int stage = c % NSTAGE;
        cp_wait1();
        __syncthreads();
        load_chunk(c + 2);

        const uint32_t aBase = sbase + OFF_A + stage * STAGE_BYTES + aOff;
        const uint32_t bBase = sbase + OFF_B + stage * STAGE_BYTES + bOff;

        #pragma unroll
        for (int k = 0; k < CHUNK; k += 16) {
            uint32_t af[4][4];
            uint32_t bf[4][2];
            #pragma unroll
            for (int mt = 0; mt < 4; mt++)
                ldsm_x4(af[mt], aBase + (uint32_t)(mt * 16 * SAW + k) * 2u);
            #pragma unroll
            for (int bt = 0; bt < 2; bt++) {
                uint32_t r[4];
                ldsm_x4(r, bBase + (uint32_t)(bt * 16 * SAW + k) * 2u);
                bf[2 * bt][0] = r[0]; bf[2 * bt][1] = r[1];
                bf[2 * bt + 1][0] = r[2]; bf[2 * bt + 1][1] = r[3];
            }
            #pragma unroll
            for (int mt = 0; mt < 4; mt++)
                #pragma unroll
                for (int nt = 0; nt < 4; nt++)
                    mma_16816(acc[mt][nt], af[mt], bf[nt]);
        }
    }

    // epilogue: relu(cos - 0.5); padded zero rows contribute relu(-0.5)=0
    float local = 0.f;
    #pragma unroll
    for (int mt = 0; mt < 4; mt++)
        #pragma unroll
        for (int nt = 0; nt < 4; nt++)
            #pragma unroll
            for (int q = 0; q < 4; q++)
                local += fmaxf(acc[mt][nt][q] - 0.5f, 0.0f);

    #pragma unroll
    for (int o = 16; o > 0; o >>= 1) local += __shfl_xor_sync(0xffffffffu, local, o);
    float* red = (float*)(smem + OFF_RED);
    if (lid == 0) red[wid] = local;
    __syncthreads();
    if (tid == 0) {
        float z = 0.f;
        #pragma unroll
        for (int i = 0; i < 8; i++) z += red[i];
        atomicAdd(&g_sum, (double)z);
        __threadfence();
        const unsigned nActive = (unsigned)((padL >> 7) * (padN >> 7));
        const unsigned done = atomicAdd(&g_done, 1u);
        if (done == nActive - 1u) {
            double total = *(volatile double*)&g_sum;
            out[0] = (float)((g_base + total) * invN);
        }
    }
}

extern "C" void kernel_launch(void* const* d_in, const int* in_sizes, int n_in,
                              void* d_out, int out_size) {
    const float* x = (const float*)d_in[0];
    const int* traw = (const int*)d_in[1];
    float* out = (float*)d_out;

    const int n = in_sizes[1];          // 8192
    const int gx = n / TILE;            // 64
    const double invN = 1.0 / (double)n;

    cudaFuncSetAttribute(relu_kernel, cudaFuncAttributeMaxDynamicSharedMemorySize, SMEM_TOTAL);

    prep_kernel<<<n / 8, 256>>>(x, traw, n);
    classsum_kernel<<<n / 64, 256>>>(n);
    scalar_kernel<<<1, 256>>>(n, out, invN);
    gather_kernel<<<512, 256>>>();
    relu_kernel<<<dim3(gx, gx), 256, SMEM_TOTAL>>>(out, invN);
}